// round 1
// baseline (speedup 1.0000x reference)
#include <cuda_runtime.h>

// Problem constants
#define BB 4
#define CC 32
#define DW 64
#define HH 256
#define WW 256
#define HW 65536

// Scratch (device globals: allocation-free rule)
__device__ float g_t[BB * DW * HW];    // conv1(LN(inp)) output, 64 MB
__device__ float g_xsg[BB * CC * HW];  // gate output, 32 MB
__device__ float g_part[BB * CC * 64]; // per-(b,ch,tile) partial sums
__device__ float g_s[BB * CC];         // SCA scale per (b,ch)

// ---- packed fp32x2 helpers (sm_100+) ----
__device__ __forceinline__ unsigned long long pack2(float lo, float hi) {
    unsigned long long r;
    asm("mov.b64 %0, {%1,%2};" : "=l"(r) : "f"(lo), "f"(hi));
    return r;
}
__device__ __forceinline__ float2 unpack2(unsigned long long v) {
    float lo, hi;
    asm("mov.b64 {%0,%1}, %2;" : "=f"(lo), "=f"(hi) : "l"(v));
    return make_float2(lo, hi);
}
__device__ __forceinline__ unsigned long long ffma2(unsigned long long a,
                                                    unsigned long long b,
                                                    unsigned long long c) {
    unsigned long long d;
    asm("fma.rn.f32x2 %0, %1, %2, %3;" : "=l"(d) : "l"(a), "l"(b), "l"(c));
    return d;
}

// =====================================================================
// K1: per-pixel LayerNorm(channel) + conv1 (32 -> 64), writes g_t
// =====================================================================
__global__ __launch_bounds__(128) void k1(const float* __restrict__ inp,
                                          const float* __restrict__ w1,
                                          const float* __restrict__ b1g,
                                          const float* __restrict__ n1w,
                                          const float* __restrict__ n1b) {
    __shared__ unsigned long long wp[32 * 32];  // pairs (w[2o2][c], w[2o2+1][c])
    __shared__ float snw[32], snb[32], sb[64];
    int tid = threadIdx.x;
    for (int i = tid; i < 1024; i += 128) {
        int o2 = i >> 5, c = i & 31;
        wp[i] = pack2(w1[(2 * o2) * 32 + c], w1[(2 * o2 + 1) * 32 + c]);
    }
    if (tid < 32) { snw[tid] = n1w[tid]; snb[tid] = n1b[tid]; }
    if (tid < 64) sb[tid] = b1g[tid];
    __syncthreads();

    int p = blockIdx.x * 128 + tid;
    int b = p >> 16, pix = p & 65535;
    const float* ip = inp + b * CC * HW + pix;

    float x[32];
    float s = 0.f, s2 = 0.f;
#pragma unroll
    for (int c = 0; c < 32; c++) {
        x[c] = ip[c * HW];
        s += x[c];
        s2 += x[c] * x[c];
    }
    float mu = s * (1.f / 32.f);
    float var = s2 * (1.f / 32.f) - mu * mu;
    float rstd = rsqrtf(var + 1e-6f);

    unsigned long long xd[32];
#pragma unroll
    for (int c = 0; c < 32; c++) {
        float v = (x[c] - mu) * rstd * snw[c] + snb[c];
        xd[c] = pack2(v, v);
    }

    float* op = g_t + b * DW * HW + pix;
#pragma unroll
    for (int o2 = 0; o2 < 32; o2++) {
        unsigned long long acc = pack2(sb[2 * o2], sb[2 * o2 + 1]);
#pragma unroll
        for (int c = 0; c < 32; c++) acc = ffma2(wp[o2 * 32 + c], xd[c], acc);
        float2 f = unpack2(acc);
        op[(2 * o2) * HW] = f.x;
        op[(2 * o2 + 1) * HW] = f.y;
    }
}

// =====================================================================
// K2: DDF (bilinear-upsampled per-pixel 3x3 filter) + SimpleGate
//     + per-tile partial channel sums for SCA.
// Grid: (64 tiles, 32 channel-pairs, 4 batches), 128 threads.
// Each thread: one row of the 32x32 tile, an 8-pixel segment, 2 channels.
// =====================================================================
__global__ __launch_bounds__(128) void k2(const float* __restrict__ w2g) {
    int tile = blockIdx.x;  // 0..63
    int chp = blockIdx.y;   // 0..31
    int b = blockIdx.z;
    int tyi = tile >> 3, txi = tile & 7;
    int h0 = tyi * 32, w0 = txi * 32;
    const int TSTR = 35;  // smem row stride (conflict-free)

    __shared__ float tin[2][34 * TSTR];
    __shared__ float Wc[2][9][36];  // [ch][tap][6x6 coarse window]
    __shared__ float red[4];

    int tid = threadIdx.x;

    // stage conv1-output tile + 1-px zero halo, both channels of the pair
#pragma unroll
    for (int cc = 0; cc < 2; cc++) {
        const float* src = g_t + (b * DW + chp + cc * 32) * HW;
        for (int idx = tid; idx < 34 * 34; idx += 128) {
            int r = idx / 34, c = idx - r * 34;
            int gh = h0 - 1 + r, gw = w0 - 1 + c;
            float v = 0.f;
            if ((unsigned)gh < 256u && (unsigned)gw < 256u) v = src[gh * 256 + gw];
            tin[cc][r * TSTR + c] = v;
        }
    }
    // stage the 6x6 coarse-weight window per tap per channel (clamped indices)
    {
        int ybase = 4 * tyi - 1, xbase = 4 * txi - 1;
        for (int idx = tid; idx < 648; idx += 128) {
            int cc = idx / 324;
            int rem = idx - cc * 324;
            int t = rem / 36;
            int rc = rem - t * 36;
            int rr = rc / 6, cj = rc - rr * 6;
            int ys = min(max(ybase + rr, 0), 31);
            int xs = min(max(xbase + cj, 0), 31);
            Wc[cc][t][rc] =
                w2g[(((b * 64 + chp + cc * 32) * 9 + t) * 32 + ys) * 32 + xs];
        }
    }
    __syncthreads();

    int row = tid >> 2;        // 0..31
    int seg = (tid & 3) * 8;   // 0,8,16,24
    int h = h0 + row;

    // y interpolation (uniform per thread); src = (h - 3.5)/8, exact in fp32
    float srcy = (h - 3.5f) * 0.125f;
    float y0f = floorf(srcy);
    float fy = srcy - y0f;
    int y0 = (int)y0f;
    int ybase = 4 * tyi - 1;
    int y0l = max(y0, 0) - ybase;
    int y1l = min(y0 + 1, 31) - ybase;

    // x interpolation: 8-pixel run w = 8m + i. i<4: x0=m-1, i>=4: x0=m.
    // fractional weights are compile-time constants.
    int m = 4 * txi + (seg >> 3);
    int xbase = 4 * txi - 1;
    int a0 = max(m - 1, 0) - xbase;
    int a1 = m - xbase;
    int b1i = min(m + 1, 31) - xbase;

    float acc[2][8];
#pragma unroll
    for (int cc = 0; cc < 2; cc++) {
        float ra[10], rb[10], rc[10];
#pragma unroll
        for (int k = 0; k < 10; k++) {
            ra[k] = tin[cc][row * TSTR + seg + k];
            rb[k] = tin[cc][(row + 1) * TSTR + seg + k];
            rc[k] = tin[cc][(row + 2) * TSTR + seg + k];
        }
#pragma unroll
        for (int i = 0; i < 8; i++) acc[cc][i] = 0.f;

#define TAP(RR, T, DX)                                              \
    {                                                               \
        const float* Wp = Wc[cc][T];                                \
        float v0a = Wp[y0l * 6 + a0], v0b = Wp[y1l * 6 + a0];       \
        float v1a = Wp[y0l * 6 + a1], v1b = Wp[y1l * 6 + a1];       \
        float v2a = Wp[y0l * 6 + b1i], v2b = Wp[y1l * 6 + b1i];     \
        float v0 = v0a + fy * (v0b - v0a);                          \
        float v1 = v1a + fy * (v1b - v1a);                          \
        float v2 = v2a + fy * (v2b - v2a);                          \
        float dA = v1 - v0, dB = v2 - v1;                           \
        acc[cc][0] += (v0 + 0.5625f * dA) * RR[0 + DX];             \
        acc[cc][1] += (v0 + 0.6875f * dA) * RR[1 + DX];             \
        acc[cc][2] += (v0 + 0.8125f * dA) * RR[2 + DX];             \
        acc[cc][3] += (v0 + 0.9375f * dA) * RR[3 + DX];             \
        acc[cc][4] += (v1 + 0.0625f * dB) * RR[4 + DX];             \
        acc[cc][5] += (v1 + 0.1875f * dB) * RR[5 + DX];             \
        acc[cc][6] += (v1 + 0.3125f * dB) * RR[6 + DX];             \
        acc[cc][7] += (v1 + 0.4375f * dB) * RR[7 + DX];             \
    }
        TAP(ra, 0, 0) TAP(ra, 1, 1) TAP(ra, 2, 2)
        TAP(rb, 3, 0) TAP(rb, 4, 1) TAP(rb, 5, 2)
        TAP(rc, 6, 0) TAP(rc, 7, 1) TAP(rc, 8, 2)
#undef TAP
    }

    // SimpleGate + store + tile-sum
    float g[8];
    float tsum = 0.f;
#pragma unroll
    for (int i = 0; i < 8; i++) {
        g[i] = acc[0][i] * acc[1][i];
        tsum += g[i];
    }
    float* op = g_xsg + (b * CC + chp) * HW + h * 256 + w0 + seg;
    *(float4*)(op) = make_float4(g[0], g[1], g[2], g[3]);
    *(float4*)(op + 4) = make_float4(g[4], g[5], g[6], g[7]);

#pragma unroll
    for (int off = 16; off; off >>= 1)
        tsum += __shfl_xor_sync(0xffffffffu, tsum, off);
    if ((tid & 31) == 0) red[tid >> 5] = tsum;
    __syncthreads();
    if (tid == 0)
        g_part[(b * CC + chp) * 64 + tile] = red[0] + red[1] + red[2] + red[3];
}

// =====================================================================
// K3: deterministic reduction of partials + SCA 1x1 conv -> g_s
// =====================================================================
__global__ void k3(const float* __restrict__ sw, const float* __restrict__ sbias) {
    __shared__ float mean_sm[128];
    int tid = threadIdx.x;  // 128 = 4 batches x 32 channels
    int b = tid >> 5, c = tid & 31;
    float sum = 0.f;
    for (int t = 0; t < 64; t++) sum += g_part[(b * CC + c) * 64 + t];
    mean_sm[tid] = sum * (1.f / 65536.f);
    __syncthreads();
    float acc = sbias[c];
#pragma unroll
    for (int k = 0; k < 32; k++) acc += sw[c * 32 + k] * mean_sm[b * 32 + k];
    g_s[tid] = acc;
}

// =====================================================================
// K4: x*s -> conv3 -> y = inp + beta*x -> LN2 -> conv4 -> gate -> conv5
//     -> out = y + gamma*z
// =====================================================================
__global__ __launch_bounds__(128) void k4(const float* __restrict__ inp,
                                          const float* __restrict__ w3,
                                          const float* __restrict__ b3g,
                                          const float* __restrict__ w4,
                                          const float* __restrict__ b4g,
                                          const float* __restrict__ w5,
                                          const float* __restrict__ b5g,
                                          const float* __restrict__ n2wg,
                                          const float* __restrict__ n2bg,
                                          const float* __restrict__ betag,
                                          const float* __restrict__ gammag,
                                          float* __restrict__ out) {
    __shared__ unsigned long long w3p[16 * 32];  // pairs (2o2, 2o2+1)
    __shared__ unsigned long long w4p[32 * 32];  // pairs (o, o+32): gate-ready
    __shared__ unsigned long long w5p[16 * 32];
    __shared__ unsigned long long b4p[32];
    __shared__ float sv[32], n2w[32], n2b[32], bet[32], gam[32], b3s[32], b5s[32];

    int tid = threadIdx.x;
    int p = blockIdx.x * 128 + tid;
    int b = p >> 16, pix = p & 65535;

    for (int i = tid; i < 512; i += 128) {
        int o2 = i >> 5, c = i & 31;
        w3p[i] = pack2(w3[(2 * o2) * 32 + c], w3[(2 * o2 + 1) * 32 + c]);
        w5p[i] = pack2(w5[(2 * o2) * 32 + c], w5[(2 * o2 + 1) * 32 + c]);
    }
    for (int i = tid; i < 1024; i += 128) {
        int o = i >> 5, c = i & 31;
        w4p[i] = pack2(w4[o * 32 + c], w4[(o + 32) * 32 + c]);
    }
    if (tid < 32) {
        sv[tid] = g_s[b * 32 + tid];
        n2w[tid] = n2wg[tid];
        n2b[tid] = n2bg[tid];
        bet[tid] = betag[tid];
        gam[tid] = gammag[tid];
        b3s[tid] = b3g[tid];
        b5s[tid] = b5g[tid];
        b4p[tid] = pack2(b4g[tid], b4g[tid + 32]);
    }
    __syncthreads();

    // x = gate_out * s
    unsigned long long xd[32];
#pragma unroll
    for (int c = 0; c < 32; c++) {
        float v = g_xsg[(b * CC + c) * HW + pix] * sv[c];
        xd[c] = pack2(v, v);
    }

    // conv3 + residual with beta
    float y[32];
    const float* ip = inp + b * CC * HW + pix;
#pragma unroll
    for (int o2 = 0; o2 < 16; o2++) {
        unsigned long long acc = pack2(b3s[2 * o2], b3s[2 * o2 + 1]);
#pragma unroll
        for (int c = 0; c < 32; c++) acc = ffma2(w3p[o2 * 32 + c], xd[c], acc);
        float2 f = unpack2(acc);
        y[2 * o2] = ip[(2 * o2) * HW] + bet[2 * o2] * f.x;
        y[2 * o2 + 1] = ip[(2 * o2 + 1) * HW] + bet[2 * o2 + 1] * f.y;
    }

    // LN2
    float s = 0.f, s2 = 0.f;
#pragma unroll
    for (int c = 0; c < 32; c++) {
        s += y[c];
        s2 += y[c] * y[c];
    }
    float mu = s * (1.f / 32.f);
    float var = s2 * (1.f / 32.f) - mu * mu;
    float rstd = rsqrtf(var + 1e-6f);
#pragma unroll
    for (int c = 0; c < 32; c++) {
        float v = (y[c] - mu) * rstd * n2w[c] + n2b[c];
        xd[c] = pack2(v, v);
    }

    // conv4 with (o, o+32) pairing -> gate directly from the f32x2 halves
    float gch[32];
#pragma unroll
    for (int o = 0; o < 32; o++) {
        unsigned long long acc = b4p[o];
#pragma unroll
        for (int c = 0; c < 32; c++) acc = ffma2(w4p[o * 32 + c], xd[c], acc);
        float2 f = unpack2(acc);
        gch[o] = f.x * f.y;
    }
#pragma unroll
    for (int c = 0; c < 32; c++) xd[c] = pack2(gch[c], gch[c]);

    // conv5 + final residual with gamma
    float* op = out + b * CC * HW + pix;
#pragma unroll
    for (int o2 = 0; o2 < 16; o2++) {
        unsigned long long acc = pack2(b5s[2 * o2], b5s[2 * o2 + 1]);
#pragma unroll
        for (int c = 0; c < 32; c++) acc = ffma2(w5p[o2 * 32 + c], xd[c], acc);
        float2 f = unpack2(acc);
        op[(2 * o2) * HW] = y[2 * o2] + gam[2 * o2] * f.x;
        op[(2 * o2 + 1) * HW] = y[2 * o2 + 1] + gam[2 * o2 + 1] * f.y;
    }
}

extern "C" void kernel_launch(void* const* d_in, const int* in_sizes, int n_in,
                              void* d_out, int out_size) {
    const float* inp     = (const float*)d_in[0];
    const float* w2      = (const float*)d_in[1];
    const float* conv1_w = (const float*)d_in[2];
    const float* conv1_b = (const float*)d_in[3];
    const float* conv3_w = (const float*)d_in[4];
    const float* conv3_b = (const float*)d_in[5];
    const float* sca_w   = (const float*)d_in[6];
    const float* sca_b   = (const float*)d_in[7];
    const float* conv4_w = (const float*)d_in[8];
    const float* conv4_b = (const float*)d_in[9];
    const float* conv5_w = (const float*)d_in[10];
    const float* conv5_b = (const float*)d_in[11];
    const float* norm1_w = (const float*)d_in[12];
    const float* norm1_b = (const float*)d_in[13];
    const float* norm2_w = (const float*)d_in[14];
    const float* norm2_b = (const float*)d_in[15];
    const float* beta    = (const float*)d_in[16];
    const float* gamma   = (const float*)d_in[17];
    float* out = (float*)d_out;

    k1<<<2048, 128>>>(inp, conv1_w, conv1_b, norm1_w, norm1_b);
    k2<<<dim3(64, 32, 4), 128>>>(w2);
    k3<<<1, 128>>>(sca_w, sca_b);
    k4<<<2048, 128>>>(inp, conv3_w, conv3_b, conv4_w, conv4_b, conv5_w, conv5_b,
                      norm2_w, norm2_b, beta, gamma, out);
}